// round 3
// baseline (speedup 1.0000x reference)
#include <cuda_runtime.h>
#include <stdint.h>

// DisplaceChannel: out[b,c,y,x] = inp[b,c, y-off_y[p], x-off_x[p]] (p = c/32),
// zero where source out of [0,64). Offsets are multiples of 32 -> float4
// vectors uniformly valid/invalid, 16B alignment preserved.
//
// Grid = (CH/2, B): one block owns TWO 64x64 planes (2048 float4) of the same
// position group. 256 threads x 8 vectors, loads front-batched for MLP=8.

#define CH 288          // 9 * 32
#define H 64
#define W 64
#define W4 16           // float4 per row
#define PLANE4 1024     // H * W4

__global__ __launch_bounds__(256)
void displace_kernel(const float4* __restrict__ in,
                     const int* __restrict__ offsets,
                     float4* __restrict__ out)
{
    const int c0 = blockIdx.x << 1;    // first of 2 channels (same position p)
    const int b  = blockIdx.y;
    const int p  = c0 >> 5;

    const int off_x = __ldg(&offsets[2 * p]);
    const int off_y = __ldg(&offsets[2 * p + 1]);

    const long base = ((long)b * CH + c0) * PLANE4;
    const float4* __restrict__ src = in + base;
    float4* __restrict__ dst = out + base;

    const int t = threadIdx.x;

    float4 v[8];
    int didx[8];
#pragma unroll
    for (int j = 0; j < 8; j++) {
        const int vid = t + (j << 8);          // 0..2047
        const int pl  = vid >> 10;             // plane 0 or 1
        const int wi  = vid & (PLANE4 - 1);    // within-plane vector
        const int x4  = wi & (W4 - 1);
        const int y   = wi >> 4;
        const int sy  = y - off_y;
        const int sx  = (x4 << 2) - off_x;
        didx[j] = vid;
        v[j] = make_float4(0.f, 0.f, 0.f, 0.f);
        if ((unsigned)sy < H && (unsigned)sx < W) {
            v[j] = __ldg(&src[(pl << 10) + (sy << 4) + (sx >> 2)]);
        }
    }
#pragma unroll
    for (int j = 0; j < 8; j++) {
        __stcs(&dst[didx[j]], v[j]);           // streaming: output never re-read
    }
}

extern "C" void kernel_launch(void* const* d_in, const int* in_sizes, int n_in,
                              void* d_out, int out_size)
{
    const float4* in = (const float4*)d_in[0];
    const int* offsets = (const int*)d_in[1];
    float4* out = (float4*)d_out;

    dim3 grid(CH / 2, 16);   // (channel pairs, batch)
    displace_kernel<<<grid, 256>>>(in, offsets, out);
}